// round 7
// baseline (speedup 1.0000x reference)
#include <cuda_runtime.h>
#include <cuda_bf16.h>

#define NNODES 1024
#define NEDGES 65536
#define STATE  1024
#define HID    64
#define POOLC  256
#define INSZ   (NNODES * POOLC)
#define NH     1024
#define ACT    2

// -------- scratch --------
__device__ float g_agg[NNODES * HID];     // per-node MEAN of relu hidden
__device__ int   g_hist[NNODES];          // edge count per dst node
__device__ int   g_off[NNODES];           // exclusive prefix
__device__ int   g_cur[NNODES];           // scatter cursor
__device__ int   g_srcs[NEDGES];          // src ids sorted by dst bucket
__device__ float g_z0[INSZ];              // pooled features
__device__ float g_part[64 * 256];        // gemv partials
__device__ float g_z3[129];               // z3 + value
__device__ int   g_is64;

// -------- K0: zero + dtype detect --------
__global__ void k_zero(const int* __restrict__ ei32) {
    int i = blockIdx.x * blockDim.x + threadIdx.x;
    if (i < 64 * 256) g_part[i] = 0.f;
    if (i < NNODES)   g_hist[i] = 0;
    if (i == 0) {
        int all0 = 1;
        for (int k = 0; k < 64; k++)
            if (ei32[2 * k + 1] != 0) { all0 = 0; break; }
        g_is64 = all0;
    }
}

// -------- K1a: histogram of dst --------
__global__ __launch_bounds__(256) void k_hist(const int* __restrict__ ei) {
    int e = blockIdx.x * blockDim.x + threadIdx.x;
    int d;
    if (g_is64) d = (int)((const long long*)ei)[NEDGES + e];
    else        d = ei[NEDGES + e];
    atomicAdd(&g_hist[d & (NNODES - 1)], 1);
}

// -------- K1b: exclusive scan (1 block, 1024 threads) --------
__global__ __launch_bounds__(1024) void k_scan() {
    __shared__ int sh[1024];
    int t = threadIdx.x;
    int orig = g_hist[t];
    sh[t] = orig;
    __syncthreads();
#pragma unroll
    for (int d = 1; d < 1024; d <<= 1) {
        int v = (t >= d) ? sh[t - d] : 0;
        __syncthreads();
        sh[t] += v;
        __syncthreads();
    }
    int excl = sh[t] - orig;
    g_off[t] = excl;
    g_cur[t] = excl;
}

// -------- K1c: scatter srcs into dst buckets --------
__global__ __launch_bounds__(256) void k_scatter(const int* __restrict__ ei) {
    int e = blockIdx.x * blockDim.x + threadIdx.x;
    int s, d;
    if (g_is64) {
        const long long* e64 = (const long long*)ei;
        s = (int)e64[e];
        d = (int)e64[NEDGES + e];
    } else {
        s = ei[e];
        d = ei[NEDGES + e];
    }
    d &= (NNODES - 1);
    int pos = atomicAdd(&g_cur[d], 1);
    g_srcs[pos] = s & (NNODES - 1);
}

// -------- K1d: per-node hidden mean (block = node, thread = channel) --------
__global__ __launch_bounds__(64) void k_nodeagg(const float* __restrict__ x,
                                                const float* __restrict__ W1,
                                                const float* __restrict__ b1) {
    __shared__ float su[64], sv[64];
    int n = blockIdx.x;
    int c = threadIdx.x;
    int cnt = g_hist[n];
    int off = g_off[n];

    float xi0 = x[2 * n], xi1 = x[2 * n + 1];
    float w2 = W1[2 * HID + c], w3 = W1[3 * HID + c];
    float base = b1[c] + xi0 * W1[c] + xi1 * W1[HID + c];

    float acc = 0.f;
    for (int b0 = 0; b0 < cnt; b0 += 64) {
        int i = b0 + c;
        if (i < cnt) {
            int s = g_srcs[off + i];
            su[c] = x[2 * s] - xi0;
            sv[c] = x[2 * s + 1] - xi1;
        }
        __syncthreads();
        int m = min(64, cnt - b0);
        for (int j = 0; j < m; j++)
            acc += fmaxf(base + su[j] * w2 + sv[j] * w3, 0.f);
        __syncthreads();
    }
    g_agg[n * HID + c] = (cnt > 0) ? acc / (float)cnt : 0.f;
}

// -------- K2: mean-hidden @W2 (cols pooled by 4) -> z0 --------
__global__ __launch_bounds__(256) void k_pool(const float* __restrict__ W2,
                                              const float* __restrict__ b2) {
    __shared__ float mh[64][HID];
    __shared__ float has[64];
    int t = threadIdx.x;
    int node0 = blockIdx.x * 64;

    for (int i = t; i < 64 * HID; i += 256)
        ((float*)mh)[i] = g_agg[node0 * HID + i];
    if (t < 64) has[t] = (g_hist[node0 + t] > 0) ? 1.f : 0.f;
    __syncthreads();

    float w2p[HID];
#pragma unroll
    for (int k = 0; k < HID; k++) {
        float4 v = *(const float4*)&W2[k * STATE + 4 * t];
        w2p[k] = 0.25f * (v.x + v.y + v.z + v.w);
    }
    float4 bb = *(const float4*)&b2[4 * t];
    float b2p = 0.25f * (bb.x + bb.y + bb.z + bb.w);

    for (int n = 0; n < 64; n++) {
        float acc = 0.f;
#pragma unroll
        for (int k = 0; k < HID; k++) acc += mh[n][k] * w2p[k];
        g_z0[(node0 + n) * POOLC + t] = acc + b2p * has[n];
    }
}

// -------- K3: split-K GEMV z0 @ W3[262144,256] --------
__global__ __launch_bounds__(256, 4) void k_gemv(const float* __restrict__ W3) {
    __shared__ float sz[256];
    __shared__ float part[4][256];
    int t = threadIdx.x;
    int k0 = blockIdx.x * 256;
    sz[t] = g_z0[k0 + t];
    __syncthreads();

    int q = t >> 6, c = t & 63;
    float4 acc = make_float4(0.f, 0.f, 0.f, 0.f);
    const float* base = W3 + (size_t)(k0 + q) * 256 + 4 * c;
#pragma unroll 8
    for (int k = 0; k < 64; k++) {
        float4 w = __ldcs((const float4*)(base + (size_t)k * 1024));
        float z = sz[4 * k + q];
        acc.x += z * w.x;
        acc.y += z * w.y;
        acc.z += z * w.z;
        acc.w += z * w.w;
    }
    ((float4*)part[q])[c] = acc;
    __syncthreads();

    float s = part[0][t] + part[1][t] + part[2][t] + part[3][t];
    atomicAdd(&g_part[(blockIdx.x & 63) * 256 + t], s);
}

// -------- K4: trunk (reduce partials -> b3 -> W4 -> W5 -> value) --------
__global__ __launch_bounds__(1024) void k_trunk(const float* __restrict__ b3,
                                                const float* __restrict__ W4,
                                                const float* __restrict__ b4,
                                                const float* __restrict__ W5,
                                                const float* __restrict__ b5,
                                                const float* __restrict__ Wv,
                                                const float* __restrict__ bv) {
    __shared__ float z1[256];
    __shared__ float z2[256];
    __shared__ float part[4][256];
    __shared__ float z3s[128];
    int t = threadIdx.x;

    // reduce g_part (4 threads per column)
    {
        int q = t >> 8, c = t & 255;
        float a = 0.f;
#pragma unroll
        for (int j = q; j < 64; j += 4) a += g_part[j * 256 + c];
        part[q][c] = a;
    }
    __syncthreads();
    if (t < 256) {
        float v = part[0][t] + part[1][t] + part[2][t] + part[3][t] + b3[t];
        z1[t] = (v > 0.f) ? v : 0.01f * v;
    }
    __syncthreads();

    {
        int q = t >> 8, c = t & 255;
        float a = 0.f;
#pragma unroll 8
        for (int k = 0; k < 64; k++) a += z1[q * 64 + k] * W4[(q * 64 + k) * 256 + c];
        part[q][c] = a;
    }
    __syncthreads();
    if (t < 256) {
        float v = part[0][t] + part[1][t] + part[2][t] + part[3][t] + b4[t];
        z2[t] = (v > 0.f) ? v : 0.01f * v;
    }
    __syncthreads();

    {
        int q = t >> 7, c = t & 127;
        float a = 0.f;
#pragma unroll 8
        for (int k = 0; k < 32; k++) a += z2[q * 32 + k] * W5[(q * 32 + k) * 128 + c];
        ((float*)part)[q * 128 + c] = a;
    }
    __syncthreads();
    if (t < 128) {
        float v = b5[t];
#pragma unroll
        for (int j = 0; j < 8; j++) v += ((float*)part)[j * 128 + t];
        v = (v > 0.f) ? v : 0.01f * v;
        z3s[t] = v;
        g_z3[t] = v;
    }
    __syncthreads();

    if (t < 32) {
        float v = 0.f;
#pragma unroll
        for (int k = t; k < 128; k += 32) v += z3s[k] * Wv[k];
#pragma unroll
        for (int off = 16; off; off >>= 1) v += __shfl_down_sync(0xFFFFFFFFu, v, off);
        if (t == 0) g_z3[128] = v + bv[0];
    }
}

// -------- K5: dueling heads --------
__global__ __launch_bounds__(256) void k_q(const float* __restrict__ Wa,
                                           const float* __restrict__ ba,
                                           float* __restrict__ out) {
    __shared__ float z3[129];
    int t = threadIdx.x;
    if (t < 129) z3[t] = g_z3[t];
    __syncthreads();

    int warp = t >> 5, lane = t & 31;
    int n = blockIdx.x * 8 + warp;

    const float4* w = (const float4*)(Wa + (size_t)n * 256);
    float4 u = w[lane];
    float4 v = w[lane + 32];
    int f = 2 * lane;
    float a0 = z3[f] * u.x + z3[f + 1] * u.z + z3[64 + f] * v.x + z3[65 + f] * v.z;
    float a1 = z3[f] * u.y + z3[f + 1] * u.w + z3[64 + f] * v.y + z3[65 + f] * v.w;
#pragma unroll
    for (int off = 16; off; off >>= 1) {
        a0 += __shfl_down_sync(0xFFFFFFFFu, a0, off);
        a1 += __shfl_down_sync(0xFFFFFFFFu, a1, off);
    }
    if (lane == 0) {
        float adv0 = a0 + ba[2 * n];
        float adv1 = a1 + ba[2 * n + 1];
        float val = z3[128];
        float m = 0.5f * (adv0 + adv1);
        out[2 * n]     = val + adv0 - m;
        out[2 * n + 1] = val + adv1 - m;
    }
}

extern "C" void kernel_launch(void* const* d_in, const int* in_sizes, int n_in,
                              void* d_out, int out_size) {
    const float* x   = (const float*)d_in[0];
    const int*   ei  = (const int*)d_in[1];
    const float* W1  = (const float*)d_in[2];
    const float* b1  = (const float*)d_in[3];
    const float* W2  = (const float*)d_in[4];
    const float* b2  = (const float*)d_in[5];
    const float* W3  = (const float*)d_in[6];
    const float* b3  = (const float*)d_in[7];
    const float* W4  = (const float*)d_in[8];
    const float* b4  = (const float*)d_in[9];
    const float* W5  = (const float*)d_in[10];
    const float* b5  = (const float*)d_in[11];
    const float* Wv  = (const float*)d_in[12];
    const float* bv  = (const float*)d_in[13];
    const float* Wa  = (const float*)d_in[14];
    const float* ba  = (const float*)d_in[15];
    float* out = (float*)d_out;

    k_zero<<<64, 256>>>(ei);
    k_hist<<<NEDGES / 256, 256>>>(ei);
    k_scan<<<1, 1024>>>();
    k_scatter<<<NEDGES / 256, 256>>>(ei);
    k_nodeagg<<<NNODES, 64>>>(x, W1, b1);
    k_pool<<<NNODES / 64, 256>>>(W2, b2);
    k_gemv<<<INSZ / 256, 256>>>(W3);
    k_trunk<<<1, 1024>>>(b3, W4, b4, W5, b5, Wv, bv);
    k_q<<<NH / 8, 256>>>(Wa, ba, out);
}

// round 8
// speedup vs baseline: 1.3961x; 1.3961x over previous
#include <cuda_runtime.h>
#include <cuda_bf16.h>

#define NNODES 1024
#define NEDGES 65536
#define STATE  1024
#define HID    64
#define POOLC  256
#define INSZ   (NNODES * POOLC)
#define NH     1024
#define ACT    2

// -------- scratch --------
__device__ float g_agg[NNODES * HID];   // segment-sum of relu hidden
__device__ float g_cnt[NNODES];
__device__ float g_z0[INSZ];
__device__ float g_part[64 * 256];      // gemv partials
__device__ float g_z3[129];
__device__ int   g_is64;

// -------- K0: zero + dtype detect --------
__global__ void k_zero(const int* __restrict__ ei32) {
    int i = blockIdx.x * blockDim.x + threadIdx.x;
    if (i < NNODES * HID) g_agg[i] = 0.f;
    if (i < NNODES)       g_cnt[i] = 0.f;
    if (i < 64 * 256)     g_part[i] = 0.f;
    if (i == 0) {
        int all0 = 1;
        for (int k = 0; k < 64; k++)
            if (ei32[2 * k + 1] != 0) { all0 = 0; break; }
        g_is64 = all0;
    }
}

// -------- K1: EdgeConv aggregation (float4 RED) --------
// thread handles (edge e = gid>>4, channel group g = gid&15)
__global__ __launch_bounds__(256) void k_edge(const float* __restrict__ x,
                                              const int* __restrict__ ei,
                                              const float* __restrict__ W1,
                                              const float* __restrict__ b1) {
    __shared__ float4 sW1[4][16];
    __shared__ float4 sb1[16];
    int t = threadIdx.x;
    if (t < 64) ((float4*)sW1)[t] = ((const float4*)W1)[t];
    if (t < 16) sb1[t] = ((const float4*)b1)[t];
    __syncthreads();

    int gid = blockIdx.x * blockDim.x + t;
    int e = gid >> 4;
    int g = gid & 15;

    int s, d;
    if (g_is64) {
        const long long* e64 = (const long long*)ei;
        s = (int)e64[e];
        d = (int)e64[NEDGES + e];
    } else {
        s = ei[e];
        d = ei[NEDGES + e];
    }
    s &= (NNODES - 1);
    d &= (NNODES - 1);

    float xi0 = x[2 * d], xi1 = x[2 * d + 1];
    float dx = x[2 * s] - xi0;
    float dy = x[2 * s + 1] - xi1;

    float4 w0 = sW1[0][g], w1 = sW1[1][g], w2 = sW1[2][g], w3 = sW1[3][g];
    float4 b = sb1[g];
    float4 h;
    h.x = fmaxf(b.x + xi0 * w0.x + xi1 * w1.x + dx * w2.x + dy * w3.x, 0.f);
    h.y = fmaxf(b.y + xi0 * w0.y + xi1 * w1.y + dx * w2.y + dy * w3.y, 0.f);
    h.z = fmaxf(b.z + xi0 * w0.z + xi1 * w1.z + dx * w2.z + dy * w3.z, 0.f);
    h.w = fmaxf(b.w + xi0 * w0.w + xi1 * w1.w + dx * w2.w + dy * w3.w, 0.f);

    atomicAdd((float4*)&g_agg[d * HID + 4 * g], h);
    if (g == 0) atomicAdd(&g_cnt[d], 1.0f);
}

// -------- K2: mean -> @W2 (cols pooled by 4) -> z0 --------
// 64 blocks x 256 threads; block handles 16 nodes; thread = pooled col
__global__ __launch_bounds__(256) void k_pool(const float* __restrict__ W2,
                                              const float* __restrict__ b2) {
    __shared__ float mh[16][HID];
    __shared__ float has[16];
    int t = threadIdx.x;
    int node0 = blockIdx.x * 16;

    for (int i = t; i < 16 * HID; i += 256) {
        int n = i >> 6, k = i & 63;
        float cnt = g_cnt[node0 + n];
        mh[n][k] = g_agg[(node0 + n) * HID + k] / fmaxf(cnt, 1.0f);
    }
    if (t < 16) has[t] = (g_cnt[node0 + t] > 0.f) ? 1.f : 0.f;
    __syncthreads();

    float w2p[HID];
#pragma unroll
    for (int k = 0; k < HID; k++) {
        float4 v = *(const float4*)&W2[k * STATE + 4 * t];
        w2p[k] = 0.25f * (v.x + v.y + v.z + v.w);
    }
    float4 bb = *(const float4*)&b2[4 * t];
    float b2p = 0.25f * (bb.x + bb.y + bb.z + bb.w);

#pragma unroll
    for (int n = 0; n < 16; n++) {
        float acc = 0.f;
#pragma unroll
        for (int k = 0; k < HID; k++) acc += mh[n][k] * w2p[k];
        g_z0[(node0 + n) * POOLC + t] = acc + b2p * has[n];
    }
}

// -------- K3: split-K GEMV z0 @ W3[262144,256] --------
// 512 blocks (ONE resident wave at occ 4) x 256 threads; 512 k-rows/block
// thread (q=t>>6, c=t&63): rows k0+4k+q, cols 4c..4c+3; two acc chains
__global__ __launch_bounds__(256, 4) void k_gemv(const float* __restrict__ W3) {
    __shared__ float sz[512];
    __shared__ float part[4][256];
    int t = threadIdx.x;
    int k0 = blockIdx.x * 512;
    sz[t] = g_z0[k0 + t];
    sz[t + 256] = g_z0[k0 + t + 256];
    __syncthreads();

    int q = t >> 6, c = t & 63;
    float4 acc0 = make_float4(0.f, 0.f, 0.f, 0.f);
    float4 acc1 = make_float4(0.f, 0.f, 0.f, 0.f);
    const float* base = W3 + (size_t)(k0 + q) * 256 + 4 * c;
#pragma unroll 8
    for (int k = 0; k < 128; k += 2) {
        float4 wa = __ldcs((const float4*)(base + (size_t)k * 1024));
        float4 wb = __ldcs((const float4*)(base + (size_t)(k + 1) * 1024));
        float za = sz[4 * k + q];
        float zb = sz[4 * k + 4 + q];
        acc0.x += za * wa.x; acc0.y += za * wa.y;
        acc0.z += za * wa.z; acc0.w += za * wa.w;
        acc1.x += zb * wb.x; acc1.y += zb * wb.y;
        acc1.z += zb * wb.z; acc1.w += zb * wb.w;
    }
    acc0.x += acc1.x; acc0.y += acc1.y; acc0.z += acc1.z; acc0.w += acc1.w;
    ((float4*)part[q])[c] = acc0;
    __syncthreads();

    float s = part[0][t] + part[1][t] + part[2][t] + part[3][t];
    atomicAdd(&g_part[(blockIdx.x & 63) * 256 + t], s);
}

// -------- K4: trunk (reduce partials -> b3 -> W4 -> W5 -> value) --------
__global__ __launch_bounds__(1024) void k_trunk(const float* __restrict__ b3,
                                                const float* __restrict__ W4,
                                                const float* __restrict__ b4,
                                                const float* __restrict__ W5,
                                                const float* __restrict__ b5,
                                                const float* __restrict__ Wv,
                                                const float* __restrict__ bv) {
    __shared__ float z1[256];
    __shared__ float z2[256];
    __shared__ float part[4][256];
    __shared__ float z3s[128];
    int t = threadIdx.x;

    {
        int q = t >> 8, c = t & 255;
        float a = 0.f;
#pragma unroll
        for (int j = q; j < 64; j += 4) a += g_part[j * 256 + c];
        part[q][c] = a;
    }
    __syncthreads();
    if (t < 256) {
        float v = part[0][t] + part[1][t] + part[2][t] + part[3][t] + b3[t];
        z1[t] = (v > 0.f) ? v : 0.01f * v;
    }
    __syncthreads();

    {
        int q = t >> 8, c = t & 255;
        float a = 0.f;
#pragma unroll 8
        for (int k = 0; k < 64; k++) a += z1[q * 64 + k] * W4[(q * 64 + k) * 256 + c];
        part[q][c] = a;
    }
    __syncthreads();
    if (t < 256) {
        float v = part[0][t] + part[1][t] + part[2][t] + part[3][t] + b4[t];
        z2[t] = (v > 0.f) ? v : 0.01f * v;
    }
    __syncthreads();

    {
        int q = t >> 7, c = t & 127;
        float a = 0.f;
#pragma unroll 8
        for (int k = 0; k < 32; k++) a += z2[q * 32 + k] * W5[(q * 32 + k) * 128 + c];
        ((float*)part)[q * 128 + c] = a;
    }
    __syncthreads();
    if (t < 128) {
        float v = b5[t];
#pragma unroll
        for (int j = 0; j < 8; j++) v += ((float*)part)[j * 128 + t];
        v = (v > 0.f) ? v : 0.01f * v;
        z3s[t] = v;
        g_z3[t] = v;
    }
    __syncthreads();

    if (t < 32) {
        float v = 0.f;
#pragma unroll
        for (int k = t; k < 128; k += 32) v += z3s[k] * Wv[k];
#pragma unroll
        for (int off = 16; off; off >>= 1) v += __shfl_down_sync(0xFFFFFFFFu, v, off);
        if (t == 0) g_z3[128] = v + bv[0];
    }
}

// -------- K5: dueling heads --------
__global__ __launch_bounds__(256) void k_q(const float* __restrict__ Wa,
                                           const float* __restrict__ ba,
                                           float* __restrict__ out) {
    __shared__ float z3[129];
    int t = threadIdx.x;
    if (t < 129) z3[t] = g_z3[t];
    __syncthreads();

    int warp = t >> 5, lane = t & 31;
    int n = blockIdx.x * 8 + warp;

    const float4* w = (const float4*)(Wa + (size_t)n * 256);
    float4 u = w[lane];
    float4 v = w[lane + 32];
    int f = 2 * lane;
    float a0 = z3[f] * u.x + z3[f + 1] * u.z + z3[64 + f] * v.x + z3[65 + f] * v.z;
    float a1 = z3[f] * u.y + z3[f + 1] * u.w + z3[64 + f] * v.y + z3[65 + f] * v.w;
#pragma unroll
    for (int off = 16; off; off >>= 1) {
        a0 += __shfl_down_sync(0xFFFFFFFFu, a0, off);
        a1 += __shfl_down_sync(0xFFFFFFFFu, a1, off);
    }
    if (lane == 0) {
        float adv0 = a0 + ba[2 * n];
        float adv1 = a1 + ba[2 * n + 1];
        float val = z3[128];
        float m = 0.5f * (adv0 + adv1);
        out[2 * n]     = val + adv0 - m;
        out[2 * n + 1] = val + adv1 - m;
    }
}

extern "C" void kernel_launch(void* const* d_in, const int* in_sizes, int n_in,
                              void* d_out, int out_size) {
    const float* x   = (const float*)d_in[0];
    const int*   ei  = (const int*)d_in[1];
    const float* W1  = (const float*)d_in[2];
    const float* b1  = (const float*)d_in[3];
    const float* W2  = (const float*)d_in[4];
    const float* b2  = (const float*)d_in[5];
    const float* W3  = (const float*)d_in[6];
    const float* b3  = (const float*)d_in[7];
    const float* W4  = (const float*)d_in[8];
    const float* b4  = (const float*)d_in[9];
    const float* W5  = (const float*)d_in[10];
    const float* b5  = (const float*)d_in[11];
    const float* Wv  = (const float*)d_in[12];
    const float* bv  = (const float*)d_in[13];
    const float* Wa  = (const float*)d_in[14];
    const float* ba  = (const float*)d_in[15];
    float* out = (float*)d_out;

    k_zero<<<(NNODES * HID + 255) / 256, 256>>>(ei);
    k_edge<<<(NEDGES * 16) / 256, 256>>>(x, ei, W1, b1);
    k_pool<<<NNODES / 16, 256>>>(W2, b2);
    k_gemv<<<INSZ / 512, 256>>>(W3);
    k_trunk<<<1, 1024>>>(b3, W4, b4, W5, b5, Wv, bv);
    k_q<<<NH / 8, 256>>>(Wa, ba, out);
}

// round 9
// speedup vs baseline: 1.4012x; 1.0037x over previous
#include <cuda_runtime.h>
#include <cuda_bf16.h>

#define NNODES 1024
#define NEDGES 65536
#define STATE  1024
#define HID    64
#define POOLC  256
#define INSZ   (NNODES * POOLC)
#define NH     1024
#define ACT    2

// -------- scratch --------
__device__ float g_agg4[4][NNODES * HID]; // 4-replica segment-sum of relu hidden
__device__ float g_cnt[NNODES];
__device__ float g_z0[INSZ];
__device__ float g_part[64 * 256];        // gemv partials
__device__ float g_acc4[256];             // W4 partial accumulator
__device__ float g_acc5[128];             // W5 partial accumulator
__device__ float g_z3[129];
__device__ int   g_is64;

// -------- K0: zero + dtype detect --------
__global__ void k_zero(const int* __restrict__ ei32) {
    int i = blockIdx.x * blockDim.x + threadIdx.x;
    if (i < 4 * NNODES * HID) ((float*)g_agg4)[i] = 0.f;
    if (i < NNODES)   g_cnt[i] = 0.f;
    if (i < 64 * 256) g_part[i] = 0.f;
    if (i < 256)      g_acc4[i] = 0.f;
    if (i < 128)      g_acc5[i] = 0.f;
    if (i == 0) {
        int all0 = 1;
        for (int k = 0; k < 64; k++)
            if (ei32[2 * k + 1] != 0) { all0 = 0; break; }
        g_is64 = all0;
    }
}

// -------- K1: EdgeConv aggregation (float4 RED, 4 replicas) --------
__global__ __launch_bounds__(256) void k_edge(const float* __restrict__ x,
                                              const int* __restrict__ ei,
                                              const float* __restrict__ W1,
                                              const float* __restrict__ b1) {
    __shared__ float4 sW1[4][16];
    __shared__ float4 sb1[16];
    int t = threadIdx.x;
    if (t < 64) ((float4*)sW1)[t] = ((const float4*)W1)[t];
    if (t < 16) sb1[t] = ((const float4*)b1)[t];
    __syncthreads();

    int gid = blockIdx.x * blockDim.x + t;
    int e = gid >> 4;
    int g = gid & 15;
    int r = blockIdx.x & 3;

    int s, d;
    if (g_is64) {
        const long long* e64 = (const long long*)ei;
        s = (int)e64[e];
        d = (int)e64[NEDGES + e];
    } else {
        s = ei[e];
        d = ei[NEDGES + e];
    }
    s &= (NNODES - 1);
    d &= (NNODES - 1);

    float xi0 = x[2 * d], xi1 = x[2 * d + 1];
    float dx = x[2 * s] - xi0;
    float dy = x[2 * s + 1] - xi1;

    float4 w0 = sW1[0][g], w1 = sW1[1][g], w2 = sW1[2][g], w3 = sW1[3][g];
    float4 b = sb1[g];
    float4 h;
    h.x = fmaxf(b.x + xi0 * w0.x + xi1 * w1.x + dx * w2.x + dy * w3.x, 0.f);
    h.y = fmaxf(b.y + xi0 * w0.y + xi1 * w1.y + dx * w2.y + dy * w3.y, 0.f);
    h.z = fmaxf(b.z + xi0 * w0.z + xi1 * w1.z + dx * w2.z + dy * w3.z, 0.f);
    h.w = fmaxf(b.w + xi0 * w0.w + xi1 * w1.w + dx * w2.w + dy * w3.w, 0.f);

    atomicAdd((float4*)&g_agg4[r][d * HID + 4 * g], h);
    if (g == 0) atomicAdd(&g_cnt[d], 1.0f);
}

// -------- K2: sum replicas -> mean -> @W2 (cols pooled by 4) -> z0 --------
__global__ __launch_bounds__(256) void k_pool(const float* __restrict__ W2,
                                              const float* __restrict__ b2) {
    __shared__ float mh[16][HID];
    __shared__ float has[16];
    int t = threadIdx.x;
    int node0 = blockIdx.x * 16;

    for (int i = t; i < 16 * HID; i += 256) {
        int n = i >> 6, k = i & 63;
        int idx = (node0 + n) * HID + k;
        float v = g_agg4[0][idx] + g_agg4[1][idx] + g_agg4[2][idx] + g_agg4[3][idx];
        mh[n][k] = v / fmaxf(g_cnt[node0 + n], 1.0f);
    }
    if (t < 16) has[t] = (g_cnt[node0 + t] > 0.f) ? 1.f : 0.f;
    __syncthreads();

    float w2p[HID];
#pragma unroll
    for (int k = 0; k < HID; k++) {
        float4 v = *(const float4*)&W2[k * STATE + 4 * t];
        w2p[k] = 0.25f * (v.x + v.y + v.z + v.w);
    }
    float4 bb = *(const float4*)&b2[4 * t];
    float b2p = 0.25f * (bb.x + bb.y + bb.z + bb.w);

#pragma unroll
    for (int n = 0; n < 16; n++) {
        float acc = 0.f;
#pragma unroll
        for (int k = 0; k < HID; k++) acc += mh[n][k] * w2p[k];
        g_z0[(node0 + n) * POOLC + t] = acc + b2p * has[n];
    }
}

// -------- K3: split-K GEMV z0 @ W3[262144,256] --------
// 256 blocks (one wave at occ 2) x 256 threads; 1024 k-rows/block; 4 acc chains
__global__ __launch_bounds__(256, 2) void k_gemv(const float* __restrict__ W3) {
    __shared__ float sz[1024];
    __shared__ float part[4][256];
    int t = threadIdx.x;
    int k0 = blockIdx.x * 1024;
#pragma unroll
    for (int i = 0; i < 4; i++) sz[t + 256 * i] = g_z0[k0 + t + 256 * i];
    __syncthreads();

    int q = t >> 6, c = t & 63;
    float4 a0 = make_float4(0.f, 0.f, 0.f, 0.f);
    float4 a1 = a0, a2 = a0, a3 = a0;
    const float* base = W3 + (size_t)(k0 + q) * 256 + 4 * c;
#pragma unroll 8
    for (int k = 0; k < 256; k += 4) {
        float4 w0 = __ldcs((const float4*)(base + (size_t)(k + 0) * 1024));
        float4 w1 = __ldcs((const float4*)(base + (size_t)(k + 1) * 1024));
        float4 w2 = __ldcs((const float4*)(base + (size_t)(k + 2) * 1024));
        float4 w3 = __ldcs((const float4*)(base + (size_t)(k + 3) * 1024));
        float z0v = sz[4 * (k + 0) + q];
        float z1v = sz[4 * (k + 1) + q];
        float z2v = sz[4 * (k + 2) + q];
        float z3v = sz[4 * (k + 3) + q];
        a0.x += z0v * w0.x; a0.y += z0v * w0.y; a0.z += z0v * w0.z; a0.w += z0v * w0.w;
        a1.x += z1v * w1.x; a1.y += z1v * w1.y; a1.z += z1v * w1.z; a1.w += z1v * w1.w;
        a2.x += z2v * w2.x; a2.y += z2v * w2.y; a2.z += z2v * w2.z; a2.w += z2v * w2.w;
        a3.x += z3v * w3.x; a3.y += z3v * w3.y; a3.z += z3v * w3.z; a3.w += z3v * w3.w;
    }
    a0.x += a1.x + a2.x + a3.x;
    a0.y += a1.y + a2.y + a3.y;
    a0.z += a1.z + a2.z + a3.z;
    a0.w += a1.w + a2.w + a3.w;
    ((float4*)part[q])[c] = a0;
    __syncthreads();

    float s = part[0][t] + part[1][t] + part[2][t] + part[3][t];
    atomicAdd(&g_part[(blockIdx.x & 63) * 256 + t], s);
}

// -------- K4a: z1 = leaky(reduce(partials)+b3); partial z2 over W4 slice --------
// 32 blocks x 256 threads; block j handles W4 rows [8j, 8j+8)
__global__ __launch_bounds__(256) void k_trunk1(const float* __restrict__ b3,
                                                const float* __restrict__ W4) {
    __shared__ float z1[256];
    int t = threadIdx.x;
    float a = 0.f;
#pragma unroll
    for (int j = 0; j < 64; j++) a += g_part[j * 256 + t];
    a += b3[t];
    z1[t] = (a > 0.f) ? a : 0.01f * a;
    __syncthreads();

    int r0 = blockIdx.x * 8;
    float acc = 0.f;
#pragma unroll
    for (int k = 0; k < 8; k++) acc += z1[r0 + k] * W4[(r0 + k) * 256 + t];
    atomicAdd(&g_acc4[t], acc);
}

// -------- K4b: z2 = leaky(acc4+b4); partial z3 over W5 slice --------
// 16 blocks x 256 threads; block j handles W5 rows [16j, 16j+16)
__global__ __launch_bounds__(256) void k_trunk2(const float* __restrict__ b4,
                                                const float* __restrict__ W5) {
    __shared__ float z2[256];
    int t = threadIdx.x;
    float v = g_acc4[t] + b4[t];
    z2[t] = (v > 0.f) ? v : 0.01f * v;
    __syncthreads();

    if (t < 128) {
        int r0 = blockIdx.x * 16;
        float acc = 0.f;
#pragma unroll
        for (int k = 0; k < 16; k++) acc += z2[r0 + k] * W5[(r0 + k) * 128 + t];
        atomicAdd(&g_acc5[t], acc);
    }
}

// -------- K4c: z3 finalize + value --------
__global__ __launch_bounds__(128) void k_trunk3(const float* __restrict__ b5,
                                                const float* __restrict__ Wv,
                                                const float* __restrict__ bv) {
    __shared__ float z3s[128];
    int t = threadIdx.x;
    float v = g_acc5[t] + b5[t];
    v = (v > 0.f) ? v : 0.01f * v;
    z3s[t] = v;
    g_z3[t] = v;
    __syncthreads();

    if (t < 32) {
        float s = z3s[t] * Wv[t] + z3s[t + 32] * Wv[t + 32]
                + z3s[t + 64] * Wv[t + 64] + z3s[t + 96] * Wv[t + 96];
#pragma unroll
        for (int off = 16; off; off >>= 1) s += __shfl_down_sync(0xFFFFFFFFu, s, off);
        if (t == 0) g_z3[128] = s + bv[0];
    }
}

// -------- K5: dueling heads --------
__global__ __launch_bounds__(256) void k_q(const float* __restrict__ Wa,
                                           const float* __restrict__ ba,
                                           float* __restrict__ out) {
    __shared__ float z3[129];
    int t = threadIdx.x;
    if (t < 129) z3[t] = g_z3[t];
    __syncthreads();

    int warp = t >> 5, lane = t & 31;
    int n = blockIdx.x * 8 + warp;

    const float4* w = (const float4*)(Wa + (size_t)n * 256);
    float4 u = w[lane];
    float4 v = w[lane + 32];
    int f = 2 * lane;
    float a0 = z3[f] * u.x + z3[f + 1] * u.z + z3[64 + f] * v.x + z3[65 + f] * v.z;
    float a1 = z3[f] * u.y + z3[f + 1] * u.w + z3[64 + f] * v.y + z3[65 + f] * v.w;
#pragma unroll
    for (int off = 16; off; off >>= 1) {
        a0 += __shfl_down_sync(0xFFFFFFFFu, a0, off);
        a1 += __shfl_down_sync(0xFFFFFFFFu, a1, off);
    }
    if (lane == 0) {
        float adv0 = a0 + ba[2 * n];
        float adv1 = a1 + ba[2 * n + 1];
        float val = z3[128];
        float m = 0.5f * (adv0 + adv1);
        out[2 * n]     = val + adv0 - m;
        out[2 * n + 1] = val + adv1 - m;
    }
}

extern "C" void kernel_launch(void* const* d_in, const int* in_sizes, int n_in,
                              void* d_out, int out_size) {
    const float* x   = (const float*)d_in[0];
    const int*   ei  = (const int*)d_in[1];
    const float* W1  = (const float*)d_in[2];
    const float* b1  = (const float*)d_in[3];
    const float* W2  = (const float*)d_in[4];
    const float* b2  = (const float*)d_in[5];
    const float* W3  = (const float*)d_in[6];
    const float* b3  = (const float*)d_in[7];
    const float* W4  = (const float*)d_in[8];
    const float* b4  = (const float*)d_in[9];
    const float* W5  = (const float*)d_in[10];
    const float* b5  = (const float*)d_in[11];
    const float* Wv  = (const float*)d_in[12];
    const float* bv  = (const float*)d_in[13];
    const float* Wa  = (const float*)d_in[14];
    const float* ba  = (const float*)d_in[15];
    float* out = (float*)d_out;

    k_zero<<<1024, 256>>>(ei);
    k_edge<<<(NEDGES * 16) / 256, 256>>>(x, ei, W1, b1);
    k_pool<<<NNODES / 16, 256>>>(W2, b2);
    k_gemv<<<INSZ / 1024, 256>>>(W3);
    k_trunk1<<<32, 256>>>(b3, W4);
    k_trunk2<<<16, 256>>>(b4, W5);
    k_trunk3<<<1, 128>>>(b5, Wv, bv);
    k_q<<<NH / 8, 256>>>(Wa, ba, out);
}

// round 10
// speedup vs baseline: 1.4888x; 1.0625x over previous
#include <cuda_runtime.h>
#include <cuda_bf16.h>

#define NNODES 1024
#define NEDGES 65536
#define STATE  1024
#define HID    64
#define POOLC  256
#define INSZ   (NNODES * POOLC)
#define NH     1024
#define ACT    2

// -------- scratch --------
__device__ float g_agg4[4][NNODES * HID]; // 4-replica segment-sum of relu hidden
__device__ float g_cnt4[4][NNODES];       // 4-replica edge counts
__device__ float g_z0[INSZ];
__device__ float g_part[64 * 256];        // gemv partials
__device__ float g_acc4[256];             // W4 partial accumulator
__device__ float g_acc5[128];             // W5 partial accumulator
__device__ int   g_is64;

// -------- K0: zero + dtype detect (float4 stores) --------
// grid 272 x 256: covers (4*65536 + 4096 + 16384 + 384)/4 float4s
__global__ void k_zero(const int* __restrict__ ei32) {
    int i = blockIdx.x * blockDim.x + threadIdx.x;
    float4 z = make_float4(0.f, 0.f, 0.f, 0.f);
    if (i < NNODES * HID) ((float4*)g_agg4)[i] = z;   // 4 replicas / 4 = 65536 float4
    if (i < NNODES) ((float4*)g_cnt4)[i] = z;         // 4*1024/4
    if (i < 64 * 64) ((float4*)g_part)[i] = z;
    if (i < 64) ((float4*)g_acc4)[i] = z;
    if (i < 32) ((float4*)g_acc5)[i] = z;
    if (i == 0) {
        int all0 = 1;
        for (int k = 0; k < 64; k++)
            if (ei32[2 * k + 1] != 0) { all0 = 0; break; }
        g_is64 = all0;
    }
}

// -------- K1: EdgeConv aggregation (float4 RED, 4 replicas, 2 edges/thread) --------
__global__ __launch_bounds__(256) void k_edge(const float* __restrict__ x,
                                              const int* __restrict__ ei,
                                              const float* __restrict__ W1,
                                              const float* __restrict__ b1) {
    __shared__ float4 sW1[4][16];
    __shared__ float4 sb1[16];
    int t = threadIdx.x;
    if (t < 64) ((float4*)sW1)[t] = ((const float4*)W1)[t];
    if (t < 16) sb1[t] = ((const float4*)b1)[t];
    __syncthreads();

    int gid = blockIdx.x * blockDim.x + t;
    int g = gid & 15;
    int r = blockIdx.x & 3;
    float4 w0 = sW1[0][g], w1 = sW1[1][g], w2 = sW1[2][g], w3 = sW1[3][g];
    float4 b = sb1[g];

#pragma unroll
    for (int half = 0; half < 2; half++) {
        int e = (gid >> 4) + half * (NEDGES / 2);
        int s, d;
        if (g_is64) {
            const long long* e64 = (const long long*)ei;
            s = (int)e64[e];
            d = (int)e64[NEDGES + e];
        } else {
            s = ei[e];
            d = ei[NEDGES + e];
        }
        s &= (NNODES - 1);
        d &= (NNODES - 1);

        float xi0 = x[2 * d], xi1 = x[2 * d + 1];
        float dx = x[2 * s] - xi0;
        float dy = x[2 * s + 1] - xi1;

        float4 h;
        h.x = fmaxf(b.x + xi0 * w0.x + xi1 * w1.x + dx * w2.x + dy * w3.x, 0.f);
        h.y = fmaxf(b.y + xi0 * w0.y + xi1 * w1.y + dx * w2.y + dy * w3.y, 0.f);
        h.z = fmaxf(b.z + xi0 * w0.z + xi1 * w1.z + dx * w2.z + dy * w3.z, 0.f);
        h.w = fmaxf(b.w + xi0 * w0.w + xi1 * w1.w + dx * w2.w + dy * w3.w, 0.f);

        atomicAdd((float4*)&g_agg4[r][d * HID + 4 * g], h);
        if (g == 0) atomicAdd(&g_cnt4[r][d], 1.0f);
    }
}

// -------- K2: sum replicas -> mean -> @W2 (cols pooled by 4) -> z0 --------
__global__ __launch_bounds__(256) void k_pool(const float* __restrict__ W2,
                                              const float* __restrict__ b2) {
    __shared__ float mh[16][HID];
    __shared__ float has[16];
    int t = threadIdx.x;
    int node0 = blockIdx.x * 16;

    for (int i = t; i < 16 * HID; i += 256) {
        int n = i >> 6, k = i & 63;
        int node = node0 + n;
        int idx = node * HID + k;
        float v = g_agg4[0][idx] + g_agg4[1][idx] + g_agg4[2][idx] + g_agg4[3][idx];
        float cnt = g_cnt4[0][node] + g_cnt4[1][node] + g_cnt4[2][node] + g_cnt4[3][node];
        mh[n][k] = v / fmaxf(cnt, 1.0f);
        if (k == 0) has[n] = (cnt > 0.f) ? 1.f : 0.f;
    }
    __syncthreads();

    float w2p[HID];
#pragma unroll
    for (int k = 0; k < HID; k++) {
        float4 v = *(const float4*)&W2[k * STATE + 4 * t];
        w2p[k] = 0.25f * (v.x + v.y + v.z + v.w);
    }
    float4 bb = *(const float4*)&b2[4 * t];
    float b2p = 0.25f * (bb.x + bb.y + bb.z + bb.w);

#pragma unroll
    for (int n = 0; n < 16; n++) {
        float acc = 0.f;
#pragma unroll
        for (int k = 0; k < HID; k++) acc += mh[n][k] * w2p[k];
        g_z0[(node0 + n) * POOLC + t] = acc + b2p * has[n];
    }
}

// -------- K3: split-K GEMV z0 @ W3[262144,256] (at LTS/DRAM floor) --------
__global__ __launch_bounds__(256, 2) void k_gemv(const float* __restrict__ W3) {
    __shared__ float sz[1024];
    __shared__ float part[4][256];
    int t = threadIdx.x;
    int k0 = blockIdx.x * 1024;
#pragma unroll
    for (int i = 0; i < 4; i++) sz[t + 256 * i] = g_z0[k0 + t + 256 * i];
    __syncthreads();

    int q = t >> 6, c = t & 63;
    float4 a0 = make_float4(0.f, 0.f, 0.f, 0.f);
    float4 a1 = a0, a2 = a0, a3 = a0;
    const float* base = W3 + (size_t)(k0 + q) * 256 + 4 * c;
#pragma unroll 8
    for (int k = 0; k < 256; k += 4) {
        float4 w0 = __ldcs((const float4*)(base + (size_t)(k + 0) * 1024));
        float4 w1 = __ldcs((const float4*)(base + (size_t)(k + 1) * 1024));
        float4 w2 = __ldcs((const float4*)(base + (size_t)(k + 2) * 1024));
        float4 w3 = __ldcs((const float4*)(base + (size_t)(k + 3) * 1024));
        float z0v = sz[4 * (k + 0) + q];
        float z1v = sz[4 * (k + 1) + q];
        float z2v = sz[4 * (k + 2) + q];
        float z3v = sz[4 * (k + 3) + q];
        a0.x += z0v * w0.x; a0.y += z0v * w0.y; a0.z += z0v * w0.z; a0.w += z0v * w0.w;
        a1.x += z1v * w1.x; a1.y += z1v * w1.y; a1.z += z1v * w1.z; a1.w += z1v * w1.w;
        a2.x += z2v * w2.x; a2.y += z2v * w2.y; a2.z += z2v * w2.z; a2.w += z2v * w2.w;
        a3.x += z3v * w3.x; a3.y += z3v * w3.y; a3.z += z3v * w3.z; a3.w += z3v * w3.w;
    }
    a0.x += a1.x + a2.x + a3.x;
    a0.y += a1.y + a2.y + a3.y;
    a0.z += a1.z + a2.z + a3.z;
    a0.w += a1.w + a2.w + a3.w;
    ((float4*)part[q])[c] = a0;
    __syncthreads();

    float s = part[0][t] + part[1][t] + part[2][t] + part[3][t];
    atomicAdd(&g_part[(blockIdx.x & 63) * 256 + t], s);
}

// -------- K4a: z1 = leaky(reduce(partials)+b3); partial z2 over W4 slice --------
__global__ __launch_bounds__(256) void k_trunk1(const float* __restrict__ b3,
                                                const float* __restrict__ W4) {
    __shared__ float z1[256];
    int t = threadIdx.x;
    float a = 0.f;
#pragma unroll
    for (int j = 0; j < 64; j++) a += g_part[j * 256 + t];
    a += b3[t];
    z1[t] = (a > 0.f) ? a : 0.01f * a;
    __syncthreads();

    int r0 = blockIdx.x * 8;
    float acc = 0.f;
#pragma unroll
    for (int k = 0; k < 8; k++) acc += z1[r0 + k] * W4[(r0 + k) * 256 + t];
    atomicAdd(&g_acc4[t], acc);
}

// -------- K4b: z2 = leaky(acc4+b4); partial z3 over W5 slice --------
__global__ __launch_bounds__(256) void k_trunk2(const float* __restrict__ b4,
                                                const float* __restrict__ W5) {
    __shared__ float z2[256];
    int t = threadIdx.x;
    float v = g_acc4[t] + b4[t];
    z2[t] = (v > 0.f) ? v : 0.01f * v;
    __syncthreads();

    if (t < 128) {
        int r0 = blockIdx.x * 16;
        float acc = 0.f;
#pragma unroll
        for (int k = 0; k < 16; k++) acc += z2[r0 + k] * W5[(r0 + k) * 128 + t];
        atomicAdd(&g_acc5[t], acc);
    }
}

// -------- K5: dueling heads (computes z3+value from acc5 per block) --------
__global__ __launch_bounds__(256) void k_q(const float* __restrict__ b5,
                                           const float* __restrict__ Wv,
                                           const float* __restrict__ bv,
                                           const float* __restrict__ Wa,
                                           const float* __restrict__ ba,
                                           float* __restrict__ out) {
    __shared__ float z3[128];
    __shared__ float sval;
    int t = threadIdx.x;
    if (t < 128) {
        float v = g_acc5[t] + b5[t];
        v = (v > 0.f) ? v : 0.01f * v;
        z3[t] = v;
    }
    __syncthreads();
    if (t < 32) {
        float s = z3[t] * Wv[t] + z3[t + 32] * Wv[t + 32]
                + z3[t + 64] * Wv[t + 64] + z3[t + 96] * Wv[t + 96];
#pragma unroll
        for (int off = 16; off; off >>= 1) s += __shfl_down_sync(0xFFFFFFFFu, s, off);
        if (t == 0) sval = s + bv[0];
    }
    __syncthreads();

    int warp = t >> 5, lane = t & 31;
    int n = blockIdx.x * 8 + warp;

    const float4* w = (const float4*)(Wa + (size_t)n * 256);
    float4 u = w[lane];
    float4 v = w[lane + 32];
    int f = 2 * lane;
    float a0 = z3[f] * u.x + z3[f + 1] * u.z + z3[64 + f] * v.x + z3[65 + f] * v.z;
    float a1 = z3[f] * u.y + z3[f + 1] * u.w + z3[64 + f] * v.y + z3[65 + f] * v.w;
#pragma unroll
    for (int off = 16; off; off >>= 1) {
        a0 += __shfl_down_sync(0xFFFFFFFFu, a0, off);
        a1 += __shfl_down_sync(0xFFFFFFFFu, a1, off);
    }
    if (lane == 0) {
        float adv0 = a0 + ba[2 * n];
        float adv1 = a1 + ba[2 * n + 1];
        float val = sval;
        float m = 0.5f * (adv0 + adv1);
        out[2 * n]     = val + adv0 - m;
        out[2 * n + 1] = val + adv1 - m;
    }
}

extern "C" void kernel_launch(void* const* d_in, const int* in_sizes, int n_in,
                              void* d_out, int out_size) {
    const float* x   = (const float*)d_in[0];
    const int*   ei  = (const int*)d_in[1];
    const float* W1  = (const float*)d_in[2];
    const float* b1  = (const float*)d_in[3];
    const float* W2  = (const float*)d_in[4];
    const float* b2  = (const float*)d_in[5];
    const float* W3  = (const float*)d_in[6];
    const float* b3  = (const float*)d_in[7];
    const float* W4  = (const float*)d_in[8];
    const float* b4  = (const float*)d_in[9];
    const float* W5  = (const float*)d_in[10];
    const float* b5  = (const float*)d_in[11];
    const float* Wv  = (const float*)d_in[12];
    const float* bv  = (const float*)d_in[13];
    const float* Wa  = (const float*)d_in[14];
    const float* ba  = (const float*)d_in[15];
    float* out = (float*)d_out;

    k_zero<<<(NNODES * HID + 255) / 256, 256>>>(ei);
    k_edge<<<(NEDGES * 16) / (256 * 2), 256>>>(x, ei, W1, b1);
    k_pool<<<NNODES / 16, 256>>>(W2, b2);
    k_gemv<<<INSZ / 1024, 256>>>(W3);
    k_trunk1<<<32, 256>>>(b3, W4);
    k_trunk2<<<16, 256>>>(b4, W5);
    k_q<<<NH / 8, 256>>>(b5, Wv, bv, Wa, ba, out);
}

// round 11
// speedup vs baseline: 1.5360x; 1.0317x over previous
#include <cuda_runtime.h>
#include <cuda_bf16.h>

#define NNODES 1024
#define NEDGES 65536
#define STATE  1024
#define HID    64
#define POOLC  256
#define INSZ   (NNODES * POOLC)
#define NH     1024
#define ACT    2

// -------- scratch (zero-initialized at load; consumer-zeroed thereafter) ----
__device__ float g_agg4[4][NNODES * HID]; // zeroed by k_gemv after reading
__device__ float g_cnt4[4][NNODES];       // zeroed by k_gemv after reading
__device__ float g_w2p[HID * 256];        // pooled W2 (recomputed每 run)
__device__ float g_b2p[256];              // pooled b2
__device__ float g_part[64 * 256];        // gemv partials; zeroed by k_w2p
__device__ float g_acc4[256];             // zeroed by k_w2p
__device__ float g_acc5[128];             // zeroed by k_w2p
__device__ int   g_is64;

// -------- K0: pooled W2/b2 + scratch zero + dtype detect --------
// 64 blocks x 256 threads; block k = W2 row k
__global__ __launch_bounds__(256) void k_w2p(const float* __restrict__ W2,
                                             const float* __restrict__ b2,
                                             const int* __restrict__ ei32) {
    int k = blockIdx.x, j = threadIdx.x;
    float4 v = *(const float4*)&W2[k * STATE + 4 * j];
    g_w2p[k * 256 + j] = 0.25f * (v.x + v.y + v.z + v.w);
    g_part[k * 256 + j] = 0.f;
    if (k == 0) {
        float4 bb = *(const float4*)&b2[4 * j];
        g_b2p[j] = 0.25f * (bb.x + bb.y + bb.z + bb.w);
    }
    if (k == 1) g_acc4[j] = 0.f;
    if (k == 2 && j < 128) g_acc5[j] = 0.f;
    if (k == 3 && j == 0) {
        int all0 = 1;
        for (int i = 0; i < 64; i++)
            if (ei32[2 * i + 1] != 0) { all0 = 0; break; }
        g_is64 = all0;
    }
}

// -------- K1: EdgeConv aggregation (float4 RED, 4 replicas, 2 edges/thread) --------
__global__ __launch_bounds__(256) void k_edge(const float* __restrict__ x,
                                              const int* __restrict__ ei,
                                              const float* __restrict__ W1,
                                              const float* __restrict__ b1) {
    __shared__ float4 sW1[4][16];
    __shared__ float4 sb1[16];
    int t = threadIdx.x;
    if (t < 64) ((float4*)sW1)[t] = ((const float4*)W1)[t];
    if (t < 16) sb1[t] = ((const float4*)b1)[t];
    __syncthreads();

    int gid = blockIdx.x * blockDim.x + t;
    int g = gid & 15;
    int r = blockIdx.x & 3;
    float4 w0 = sW1[0][g], w1 = sW1[1][g], w2 = sW1[2][g], w3 = sW1[3][g];
    float4 b = sb1[g];

#pragma unroll
    for (int half = 0; half < 2; half++) {
        int e = (gid >> 4) + half * (NEDGES / 2);
        int s, d;
        if (g_is64) {
            const long long* e64 = (const long long*)ei;
            s = (int)e64[e];
            d = (int)e64[NEDGES + e];
        } else {
            s = ei[e];
            d = ei[NEDGES + e];
        }
        s &= (NNODES - 1);
        d &= (NNODES - 1);

        float xi0 = x[2 * d], xi1 = x[2 * d + 1];
        float dx = x[2 * s] - xi0;
        float dy = x[2 * s + 1] - xi1;

        float4 h;
        h.x = fmaxf(b.x + xi0 * w0.x + xi1 * w1.x + dx * w2.x + dy * w3.x, 0.f);
        h.y = fmaxf(b.y + xi0 * w0.y + xi1 * w1.y + dx * w2.y + dy * w3.y, 0.f);
        h.z = fmaxf(b.z + xi0 * w0.z + xi1 * w1.z + dx * w2.z + dy * w3.z, 0.f);
        h.w = fmaxf(b.w + xi0 * w0.w + xi1 * w1.w + dx * w2.w + dy * w3.w, 0.f);

        atomicAdd((float4*)&g_agg4[r][d * HID + 4 * g], h);
        if (g == 0) atomicAdd(&g_cnt4[r][d], 1.0f);
    }
}

// -------- K2: fused pool + split-K GEMV over W3[262144,256] --------
// 256 blocks x 256 threads; block b owns nodes 4b..4b+3 and k-rows [1024b,1024b+1024)
__global__ __launch_bounds__(256, 2) void k_gemv(const float* __restrict__ W3) {
    __shared__ float mh[4][HID];
    __shared__ float scnt[4];
    __shared__ float has[4];
    __shared__ float sz[1024];
    __shared__ float part[4][256];
    int t = threadIdx.x;
    int bb = blockIdx.x;

    // ---- prologue: build z0 slice for nodes 4bb..4bb+3 ----
    {
        int n = t >> 6, k = t & 63;
        int node = 4 * bb + n;
        int idx = node * HID + k;
        float a = g_agg4[0][idx] + g_agg4[1][idx] + g_agg4[2][idx] + g_agg4[3][idx];
        g_agg4[0][idx] = 0.f; g_agg4[1][idx] = 0.f;
        g_agg4[2][idx] = 0.f; g_agg4[3][idx] = 0.f;
        mh[n][k] = a;
        if (t < 4) {
            int nd = 4 * bb + t;
            float c = g_cnt4[0][nd] + g_cnt4[1][nd] + g_cnt4[2][nd] + g_cnt4[3][nd];
            g_cnt4[0][nd] = 0.f; g_cnt4[1][nd] = 0.f;
            g_cnt4[2][nd] = 0.f; g_cnt4[3][nd] = 0.f;
            scnt[t] = fmaxf(c, 1.0f);
            has[t] = (c > 0.f) ? 1.f : 0.f;
        }
        __syncthreads();
        mh[n][k] *= __frcp_rn(scnt[n]);
        __syncthreads();

        // thread t computes column t of z0 for all 4 nodes
        float a0 = 0.f, a1 = 0.f, a2 = 0.f, a3 = 0.f;
#pragma unroll 8
        for (int kk = 0; kk < HID; kk++) {
            float w = g_w2p[kk * 256 + t];
            a0 += mh[0][kk] * w;
            a1 += mh[1][kk] * w;
            a2 += mh[2][kk] * w;
            a3 += mh[3][kk] * w;
        }
        float bp = g_b2p[t];
        sz[t]       = a0 + bp * has[0];
        sz[256 + t] = a1 + bp * has[1];
        sz[512 + t] = a2 + bp * has[2];
        sz[768 + t] = a3 + bp * has[3];
        __syncthreads();
    }

    // ---- streaming GEMV over 1024 k-rows ----
    int k0 = bb * 1024;
    int q = t >> 6, c = t & 63;
    float4 a0 = make_float4(0.f, 0.f, 0.f, 0.f);
    float4 a1 = a0, a2 = a0, a3 = a0;
    const float* base = W3 + (size_t)(k0 + q) * 256 + 4 * c;
#pragma unroll 8
    for (int k = 0; k < 256; k += 4) {
        float4 w0 = __ldcs((const float4*)(base + (size_t)(k + 0) * 1024));
        float4 w1 = __ldcs((const float4*)(base + (size_t)(k + 1) * 1024));
        float4 w2 = __ldcs((const float4*)(base + (size_t)(k + 2) * 1024));
        float4 w3 = __ldcs((const float4*)(base + (size_t)(k + 3) * 1024));
        float z0v = sz[4 * (k + 0) + q];
        float z1v = sz[4 * (k + 1) + q];
        float z2v = sz[4 * (k + 2) + q];
        float z3v = sz[4 * (k + 3) + q];
        a0.x += z0v * w0.x; a0.y += z0v * w0.y; a0.z += z0v * w0.z; a0.w += z0v * w0.w;
        a1.x += z1v * w1.x; a1.y += z1v * w1.y; a1.z += z1v * w1.z; a1.w += z1v * w1.w;
        a2.x += z2v * w2.x; a2.y += z2v * w2.y; a2.z += z2v * w2.z; a2.w += z2v * w2.w;
        a3.x += z3v * w3.x; a3.y += z3v * w3.y; a3.z += z3v * w3.z; a3.w += z3v * w3.w;
    }
    a0.x += a1.x + a2.x + a3.x;
    a0.y += a1.y + a2.y + a3.y;
    a0.z += a1.z + a2.z + a3.z;
    a0.w += a1.w + a2.w + a3.w;
    ((float4*)part[q])[c] = a0;
    __syncthreads();

    float s = part[0][t] + part[1][t] + part[2][t] + part[3][t];
    atomicAdd(&g_part[(bb & 63) * 256 + t], s);
}

// -------- K3: z1 = leaky(reduce(partials)+b3); partial z2 over W4 slice --------
__global__ __launch_bounds__(256) void k_trunk1(const float* __restrict__ b3,
                                                const float* __restrict__ W4) {
    __shared__ float z1[256];
    int t = threadIdx.x;
    float a = 0.f;
#pragma unroll
    for (int j = 0; j < 64; j++) a += g_part[j * 256 + t];
    a += b3[t];
    z1[t] = (a > 0.f) ? a : 0.01f * a;
    __syncthreads();

    int r0 = blockIdx.x * 8;
    float acc = 0.f;
#pragma unroll
    for (int k = 0; k < 8; k++) acc += z1[r0 + k] * W4[(r0 + k) * 256 + t];
    atomicAdd(&g_acc4[t], acc);
}

// -------- K4: z2 = leaky(acc4+b4); partial z3 over W5 slice --------
__global__ __launch_bounds__(256) void k_trunk2(const float* __restrict__ b4,
                                                const float* __restrict__ W5) {
    __shared__ float z2[256];
    int t = threadIdx.x;
    float v = g_acc4[t] + b4[t];
    z2[t] = (v > 0.f) ? v : 0.01f * v;
    __syncthreads();

    if (t < 128) {
        int r0 = blockIdx.x * 16;
        float acc = 0.f;
#pragma unroll
        for (int k = 0; k < 16; k++) acc += z2[r0 + k] * W5[(r0 + k) * 128 + t];
        atomicAdd(&g_acc5[t], acc);
    }
}

// -------- K5: dueling heads (z3+value recomputed per block) --------
__global__ __launch_bounds__(256) void k_q(const float* __restrict__ b5,
                                           const float* __restrict__ Wv,
                                           const float* __restrict__ bv,
                                           const float* __restrict__ Wa,
                                           const float* __restrict__ ba,
                                           float* __restrict__ out) {
    __shared__ float z3[128];
    __shared__ float sval;
    int t = threadIdx.x;
    if (t < 128) {
        float v = g_acc5[t] + b5[t];
        v = (v > 0.f) ? v : 0.01f * v;
        z3[t] = v;
    }
    __syncthreads();
    if (t < 32) {
        float s = z3[t] * Wv[t] + z3[t + 32] * Wv[t + 32]
                + z3[t + 64] * Wv[t + 64] + z3[t + 96] * Wv[t + 96];
#pragma unroll
        for (int off = 16; off; off >>= 1) s += __shfl_down_sync(0xFFFFFFFFu, s, off);
        if (t == 0) sval = s + bv[0];
    }
    __syncthreads();

    int warp = t >> 5, lane = t & 31;
    int n = blockIdx.x * 8 + warp;

    const float4* w = (const float4*)(Wa + (size_t)n * 256);
    float4 u = w[lane];
    float4 v = w[lane + 32];
    int f = 2 * lane;
    float a0 = z3[f] * u.x + z3[f + 1] * u.z + z3[64 + f] * v.x + z3[65 + f] * v.z;
    float a1 = z3[f] * u.y + z3[f + 1] * u.w + z3[64 + f] * v.y + z3[65 + f] * v.w;
#pragma unroll
    for (int off = 16; off; off >>= 1) {
        a0 += __shfl_down_sync(0xFFFFFFFFu, a0, off);
        a1 += __shfl_down_sync(0xFFFFFFFFu, a1, off);
    }
    if (lane == 0) {
        float adv0 = a0 + ba[2 * n];
        float adv1 = a1 + ba[2 * n + 1];
        float val = sval;
        float m = 0.5f * (adv0 + adv1);
        out[2 * n]     = val + adv0 - m;
        out[2 * n + 1] = val + adv1 - m;
    }
}

extern "C" void kernel_launch(void* const* d_in, const int* in_sizes, int n_in,
                              void* d_out, int out_size) {
    const float* x   = (const float*)d_in[0];
    const int*   ei  = (const int*)d_in[1];
    const float* W1  = (const float*)d_in[2];
    const float* b1  = (const float*)d_in[3];
    const float* W2  = (const float*)d_in[4];
    const float* b2  = (const float*)d_in[5];
    const float* W3  = (const float*)d_in[6];
    const float* b3  = (const float*)d_in[7];
    const float* W4  = (const float*)d_in[8];
    const float* b4  = (const float*)d_in[9];
    const float* W5  = (const float*)d_in[10];
    const float* b5  = (const float*)d_in[11];
    const float* Wv  = (const float*)d_in[12];
    const float* bv  = (const float*)d_in[13];
    const float* Wa  = (const float*)d_in[14];
    const float* ba  = (const float*)d_in[15];
    float* out = (float*)d_out;

    k_w2p<<<64, 256>>>(W2, b2, ei);
    k_edge<<<(NEDGES * 16) / (256 * 2), 256>>>(x, ei, W1, b1);
    k_gemv<<<INSZ / 1024, 256>>>(W3);
    k_trunk1<<<32, 256>>>(b3, W4);
    k_trunk2<<<16, 256>>>(b4, W5);
    k_q<<<NH / 8, 256>>>(b5, Wv, bv, Wa, ba, out);
}